// round 2
// baseline (speedup 1.0000x reference)
#include <cuda_runtime.h>
#include <math.h>
#include <stdint.h>

// Problem dims
#define BN   64
#define TN   512
#define BT   32768       // B*T
#define DN   1536        // 2*D_BERT
#define C1   192         // conv channels each
#define C4T  768         // 4*C
#define HN   256
#define G4   1024        // 4*H
#define LBL  20

// ---------------- scratch (static device memory; no allocations) -------------
__device__ float g_xn [ (size_t)BT * DN  ];   // LN1 output
__device__ float g_cv [ (size_t)BT * C4T ];   // conv+relu output
__device__ float g_co [ (size_t)BT * C4T ];   // LN2 output
__device__ float g_gxf[ (size_t)BT * G4  ];   // x@Wx_f + bf
__device__ float g_gxb[ (size_t)BT * G4  ];   // x@Wx_b + bb
__device__ float g_h  [ (size_t)BT * 2*HN];   // [hf|hb] concat per (b,t)
__device__ float g_lg [ (size_t)BT * LBL ];   // logits

// ---------------- LayerNorm 1: concat(hid_a,hid_b) + LN over 1536 ------------
__global__ __launch_bounds__(256) void ln1_kernel(
    const float* __restrict__ ha, const float* __restrict__ hb,
    const float* __restrict__ g,  const float* __restrict__ be,
    float* __restrict__ out)
{
    int row = blockIdx.x;
    const float* A = ha + (size_t)row * 768;
    const float* B = hb + (size_t)row * 768;
    float s = 0.f, s2 = 0.f;
    for (int d = threadIdx.x; d < DN; d += 256) {
        float v = (d < 768) ? A[d] : B[d - 768];
        s += v; s2 += v * v;
    }
    __shared__ float rs[256], rq[256];
    rs[threadIdx.x] = s; rq[threadIdx.x] = s2;
    __syncthreads();
    for (int off = 128; off > 0; off >>= 1) {
        if (threadIdx.x < off) {
            rs[threadIdx.x] += rs[threadIdx.x + off];
            rq[threadIdx.x] += rq[threadIdx.x + off];
        }
        __syncthreads();
    }
    float mean = rs[0] * (1.f / DN);
    float var  = rq[0] * (1.f / DN) - mean * mean;
    float rstd = rsqrtf(var + 1e-5f);
    float* O = out + (size_t)row * DN;
    for (int d = threadIdx.x; d < DN; d += 256) {
        float v = (d < 768) ? A[d] : B[d - 768];
        O[d] = (v - mean) * rstd * g[d] + be[d];
    }
}

// ---------------- LayerNorm 2 over 768 ---------------------------------------
__global__ __launch_bounds__(256) void ln2_kernel(
    const float* __restrict__ in, const float* __restrict__ g,
    const float* __restrict__ be, float* __restrict__ out)
{
    int row = blockIdx.x;
    const float* X = in + (size_t)row * C4T;
    float s = 0.f, s2 = 0.f;
    for (int d = threadIdx.x; d < C4T; d += 256) {
        float v = X[d]; s += v; s2 += v * v;
    }
    __shared__ float rs[256], rq[256];
    rs[threadIdx.x] = s; rq[threadIdx.x] = s2;
    __syncthreads();
    for (int off = 128; off > 0; off >>= 1) {
        if (threadIdx.x < off) {
            rs[threadIdx.x] += rs[threadIdx.x + off];
            rq[threadIdx.x] += rq[threadIdx.x + off];
        }
        __syncthreads();
    }
    float mean = rs[0] * (1.f / C4T);
    float var  = rq[0] * (1.f / C4T) - mean * mean;
    float rstd = rsqrtf(var + 1e-5f);
    float* O = out + (size_t)row * C4T;
    for (int d = threadIdx.x; d < C4T; d += 256) {
        O[d] = (X[d] - mean) * rstd * g[d] + be[d];
    }
}

// ---------------- Conv (taps -1..+2) as GEMM, fused bias+ReLU ----------------
// Col tile (64 wide) lies inside one conv (192 = 3*64). Taps used per conv:
//   conv0 (w1,k=1): offset {0}        -> shift = 0
//   conv1 (w2,k=2): offsets {0,+1}
//   conv2 (w3,k=3): offsets {-1,0,+1}
//   conv3 (w4,k=4): offsets {-1,0,+1,+2}
__global__ __launch_bounds__(256) void conv_gemm_kernel(
    const float* __restrict__ xn,
    const float* __restrict__ w1, const float* __restrict__ w2,
    const float* __restrict__ w3, const float* __restrict__ w4,
    const float* __restrict__ b1, const float* __restrict__ b2,
    const float* __restrict__ b3, const float* __restrict__ b4,
    float* __restrict__ cv)
{
    __shared__ float As[16][64];
    __shared__ float Bs[16][64];
    int tid  = threadIdx.x;
    int m0   = blockIdx.x * 64;
    int ct   = blockIdx.y;          // 0..11
    int conv = ct / 3;
    int nloc0 = (ct % 3) * 64;
    int bidx = m0 >> 9;             // batch
    int t0   = m0 & 511;            // time within batch (tiles never cross b)
    const float* wbase = (conv == 0) ? w1 : (conv == 1) ? w2 : (conv == 2) ? w3 : w4;
    const float* bias  = (conv == 0) ? b1 : (conv == 1) ? b2 : (conv == 2) ? b3 : b4;
    int ntaps = conv + 1;
    int dmin  = (conv < 2) ? 1 : 0;

    int tx = tid & 15, ty = tid >> 4;
    int ar = tid >> 2, ac = (tid & 3) << 2;   // A-tile load coords
    int bk = tid >> 4, bn = (tid & 15) << 2;  // B-tile load coords

    float acc[4][4];
#pragma unroll
    for (int i = 0; i < 4; i++)
#pragma unroll
        for (int j = 0; j < 4; j++) acc[i][j] = 0.f;

    for (int ti = 0; ti < ntaps; ti++) {
        int shift = dmin + ti - 1;               // time offset in {-1,0,1,2}
        int tsrc  = t0 + ar + shift;
        bool valid = (tsrc >= 0) && (tsrc < TN);
        const float* Arow = xn + ((size_t)((bidx << 9) + (valid ? tsrc : 0))) * DN;
        const float* Wt   = wbase + (size_t)ti * DN * C1 + nloc0;

        for (int k0 = 0; k0 < DN; k0 += 16) {
            float4 av = make_float4(0.f, 0.f, 0.f, 0.f);
            if (valid) av = *reinterpret_cast<const float4*>(Arow + k0 + ac);
            As[ac + 0][ar] = av.x; As[ac + 1][ar] = av.y;
            As[ac + 2][ar] = av.z; As[ac + 3][ar] = av.w;
            float4 wv = *reinterpret_cast<const float4*>(Wt + (size_t)(k0 + bk) * C1 + bn);
            Bs[bk][bn + 0] = wv.x; Bs[bk][bn + 1] = wv.y;
            Bs[bk][bn + 2] = wv.z; Bs[bk][bn + 3] = wv.w;
            __syncthreads();
#pragma unroll
            for (int kk = 0; kk < 16; kk++) {
                float4 a = *reinterpret_cast<const float4*>(&As[kk][ty << 2]);
                float4 b = *reinterpret_cast<const float4*>(&Bs[kk][tx << 2]);
                acc[0][0] += a.x * b.x; acc[0][1] += a.x * b.y; acc[0][2] += a.x * b.z; acc[0][3] += a.x * b.w;
                acc[1][0] += a.y * b.x; acc[1][1] += a.y * b.y; acc[1][2] += a.y * b.z; acc[1][3] += a.y * b.w;
                acc[2][0] += a.z * b.x; acc[2][1] += a.z * b.y; acc[2][2] += a.z * b.z; acc[2][3] += a.z * b.w;
                acc[3][0] += a.w * b.x; acc[3][1] += a.w * b.y; acc[3][2] += a.w * b.z; acc[3][3] += a.w * b.w;
            }
            __syncthreads();
        }
    }
    int colbase  = conv * C1 + nloc0 + (tx << 2);
    int biasbase = nloc0 + (tx << 2);
#pragma unroll
    for (int i = 0; i < 4; i++) {
        int row = m0 + (ty << 2) + i;
        float* O = cv + (size_t)row * C4T + colbase;
#pragma unroll
        for (int j = 0; j < 4; j++) {
            float v = acc[i][j] + bias[biasbase + j];
            O[j] = fmaxf(v, 0.f);
        }
    }
}

// ---------------- Generic GEMM:  C = A[MxK] @ W[KxN] + bias ------------------
// Requires M%64==0, K%16==0. N arbitrary (guarded).
__global__ __launch_bounds__(256) void gemm_bias_kernel(
    const float* __restrict__ A, const float* __restrict__ W,
    const float* __restrict__ bias, float* __restrict__ C,
    int M, int N, int K)
{
    __shared__ float As[16][64];
    __shared__ float Bs[16][64];
    int tid = threadIdx.x;
    int m0 = blockIdx.x * 64, n0 = blockIdx.y * 64;
    int tx = tid & 15, ty = tid >> 4;
    int ar = tid >> 2, ac = (tid & 3) << 2;
    int bk = tid >> 4, bn = (tid & 15) << 2;

    float acc[4][4];
#pragma unroll
    for (int i = 0; i < 4; i++)
#pragma unroll
        for (int j = 0; j < 4; j++) acc[i][j] = 0.f;

    const float* Arow = A + (size_t)(m0 + ar) * K;
    for (int k0 = 0; k0 < K; k0 += 16) {
        float4 av = *reinterpret_cast<const float4*>(Arow + k0 + ac);
        As[ac + 0][ar] = av.x; As[ac + 1][ar] = av.y;
        As[ac + 2][ar] = av.z; As[ac + 3][ar] = av.w;
        float4 wv = make_float4(0.f, 0.f, 0.f, 0.f);
        int ncol = n0 + bn;
        const float* Wr = W + (size_t)(k0 + bk) * N;
        if (ncol + 3 < N) {
            wv = *reinterpret_cast<const float4*>(Wr + ncol);
        } else {
            if (ncol + 0 < N) wv.x = Wr[ncol + 0];
            if (ncol + 1 < N) wv.y = Wr[ncol + 1];
            if (ncol + 2 < N) wv.z = Wr[ncol + 2];
            if (ncol + 3 < N) wv.w = Wr[ncol + 3];
        }
        Bs[bk][bn + 0] = wv.x; Bs[bk][bn + 1] = wv.y;
        Bs[bk][bn + 2] = wv.z; Bs[bk][bn + 3] = wv.w;
        __syncthreads();
#pragma unroll
        for (int kk = 0; kk < 16; kk++) {
            float4 a = *reinterpret_cast<const float4*>(&As[kk][ty << 2]);
            float4 b = *reinterpret_cast<const float4*>(&Bs[kk][tx << 2]);
            acc[0][0] += a.x * b.x; acc[0][1] += a.x * b.y; acc[0][2] += a.x * b.z; acc[0][3] += a.x * b.w;
            acc[1][0] += a.y * b.x; acc[1][1] += a.y * b.y; acc[1][2] += a.y * b.z; acc[1][3] += a.y * b.w;
            acc[2][0] += a.z * b.x; acc[2][1] += a.z * b.y; acc[2][2] += a.z * b.z; acc[2][3] += a.z * b.w;
            acc[3][0] += a.w * b.x; acc[3][1] += a.w * b.y; acc[3][2] += a.w * b.z; acc[3][3] += a.w * b.w;
        }
        __syncthreads();
    }
#pragma unroll
    for (int i = 0; i < 4; i++) {
        int row = m0 + (ty << 2) + i;
#pragma unroll
        for (int j = 0; j < 4; j++) {
            int n = n0 + (tx << 2) + j;
            if (n < N) C[(size_t)row * N + n] = acc[i][j] + bias[n];
        }
    }
}

// ---------------- LSTM recurrence: block = (dir, batch-pair) -----------------
// 64 blocks x 512 threads. Gates z = gx + h @ Wh (bias already in gx).
__global__ __launch_bounds__(512) void lstm_kernel(
    const float* __restrict__ gxf, const float* __restrict__ gxb,
    const float* __restrict__ wh_f, const float* __restrict__ wh_b,
    const int* __restrict__ amask, float* __restrict__ hout)
{
    int blk = blockIdx.x;
    int dir = blk >> 5;
    int bp  = blk & 31;
    int b0  = bp * 2;
    const float* Wh = dir ? wh_b : wh_f;   // [256][1024]
    const float* gx = dir ? gxb : gxf;     // [BT][1024]

    __shared__ float h_s[2][HN], c_s[2][HN], op_s[2][HN];
    __shared__ float z_s[2][G4];
    int tid = threadIdx.x;
    if (tid < HN) {
        h_s[0][tid] = 0.f; c_s[0][tid] = 0.f; op_s[0][tid] = 0.f;
        h_s[1][tid] = 0.f; c_s[1][tid] = 0.f; op_s[1][tid] = 0.f;
    }
    __syncthreads();

    for (int s = 0; s < TN; s++) {
        int t = dir ? (TN - 1 - s) : s;
        size_t r0 = ((size_t)(b0 * TN + t)) * G4;
        size_t r1 = ((size_t)((b0 + 1) * TN + t)) * G4;
        float a00 = gx[r0 + tid],       a01 = gx[r0 + tid + 512];
        float a10 = gx[r1 + tid],       a11 = gx[r1 + tid + 512];
#pragma unroll 4
        for (int k = 0; k < HN; k++) {
            float w0 = Wh[k * G4 + tid];
            float w1 = Wh[k * G4 + tid + 512];
            float h0 = h_s[0][k], h1 = h_s[1][k];
            a00 += h0 * w0; a01 += h0 * w1;
            a10 += h1 * w0; a11 += h1 * w1;
        }
        z_s[0][tid] = a00; z_s[0][tid + 512] = a01;
        z_s[1][tid] = a10; z_s[1][tid + 512] = a11;
        __syncthreads();
        {
            int q = tid >> 8, j = tid & 255;
            float zi = z_s[q][j],       zf = z_s[q][j + 256];
            float zg = z_s[q][j + 512], zo = z_s[q][j + 768];
            float ii = 1.f / (1.f + expf(-zi));
            float ff = 1.f / (1.f + expf(-zf));
            float gg = tanhf(zg);
            float oo = 1.f / (1.f + expf(-zo));
            float cn = ff * c_s[q][j] + ii * gg;
            float hn = oo * tanhf(cn);
            int bb_ = b0 + q;
            bool m = amask[bb_ * TN + t] != 0;
            float hq  = m ? hn : h_s[q][j];
            float cq  = m ? cn : c_s[q][j];
            float ov  = m ? hn : op_s[q][j];
            h_s[q][j] = hq; c_s[q][j] = cq; op_s[q][j] = ov;
            hout[((size_t)(bb_ * TN + t)) * (2 * HN) + dir * HN + j] = ov;
        }
        __syncthreads();
    }
}

// ---------------- CRF log-likelihood: one warp per batch element -------------
__global__ __launch_bounds__(32) void crf_kernel(
    const int* __restrict__ inputs, const int* __restrict__ targets,
    const float* __restrict__ trans, const float* __restrict__ logits,
    float* __restrict__ out)
{
    int b = blockIdx.x;
    int lane = threadIdx.x;
    __shared__ float tr[LBL * LBL];
    __shared__ float alpha[LBL];
    for (int i = lane; i < LBL * LBL; i += 32) tr[i] = trans[i];

    // seq_len
    int cnt = 0;
    for (int t = lane; t < TN; t += 32) cnt += (inputs[b * TN + t] != 0);
#pragma unroll
    for (int o = 16; o; o >>= 1) cnt += __shfl_xor_sync(0xffffffffu, cnt, o);
    int seqlen = cnt;

    const float* lg = logits + (size_t)b * TN * LBL;
    const int*   tg = targets + b * TN;

    // unary + binary scores
    float us = 0.f, bs = 0.f;
    for (int t = lane; t < TN; t += 32) {
        if (t < seqlen) us += lg[t * LBL + tg[t]];
        if (t >= 1 && t < seqlen) bs += tr[tg[t - 1] * LBL + tg[t]];
    }
#pragma unroll
    for (int o = 16; o; o >>= 1) {
        us += __shfl_xor_sync(0xffffffffu, us, o);
        bs += __shfl_xor_sync(0xffffffffu, bs, o);
    }

    __syncwarp();
    if (lane < LBL) alpha[lane] = lg[lane];
    __syncwarp();

    for (int t = 1; t < TN; t++) {
        float newv = 0.f;
        if (lane < LBL) {
            float m = -1e30f;
#pragma unroll
            for (int i = 0; i < LBL; i++) m = fmaxf(m, alpha[i] + tr[i * LBL + lane]);
            float ss = 0.f;
#pragma unroll
            for (int i = 0; i < LBL; i++) ss += expf(alpha[i] + tr[i * LBL + lane] - m);
            newv = m + logf(ss) + lg[t * LBL + lane];
        }
        __syncwarp();
        if (lane < LBL && t < seqlen) alpha[lane] = newv;
        __syncwarp();
    }

    float a = (lane < LBL) ? alpha[lane] : -1e30f;
    float mx = a;
#pragma unroll
    for (int o = 16; o; o >>= 1) mx = fmaxf(mx, __shfl_xor_sync(0xffffffffu, mx, o));
    float e = (lane < LBL) ? expf(a - mx) : 0.f;
#pragma unroll
    for (int o = 16; o; o >>= 1) e += __shfl_xor_sync(0xffffffffu, e, o);
    float lognorm = mx + logf(e);
    if (lane == 0) out[b] = us + bs - lognorm;
}

// ---------------- launch ------------------------------------------------------
extern "C" void kernel_launch(void* const* d_in, const int* in_sizes, int n_in,
                              void* d_out, int out_size)
{
    const int*   inputs = (const int*)  d_in[0];
    const int*   amask  = (const int*)  d_in[1];
    const int*   targets= (const int*)  d_in[2];
    const float* hid_a  = (const float*)d_in[3];
    const float* hid_b  = (const float*)d_in[4];
    const float* ln1_g  = (const float*)d_in[5];
    const float* ln1_b  = (const float*)d_in[6];
    const float* w1 = (const float*)d_in[7];
    const float* b1 = (const float*)d_in[8];
    const float* w2 = (const float*)d_in[9];
    const float* b2 = (const float*)d_in[10];
    const float* w3 = (const float*)d_in[11];
    const float* b3 = (const float*)d_in[12];
    const float* w4 = (const float*)d_in[13];
    const float* b4 = (const float*)d_in[14];
    const float* ln2_g = (const float*)d_in[15];
    const float* ln2_b = (const float*)d_in[16];
    const float* wx_f  = (const float*)d_in[17];
    const float* wh_f  = (const float*)d_in[18];
    const float* bf    = (const float*)d_in[19];
    const float* wx_b  = (const float*)d_in[20];
    const float* wh_b  = (const float*)d_in[21];
    const float* bb    = (const float*)d_in[22];
    const float* wd    = (const float*)d_in[23];
    const float* bd    = (const float*)d_in[24];
    const float* trans = (const float*)d_in[25];

    float *xn, *cv, *co, *gxf, *gxb, *hh, *lg;
    cudaGetSymbolAddress((void**)&xn,  g_xn);
    cudaGetSymbolAddress((void**)&cv,  g_cv);
    cudaGetSymbolAddress((void**)&co,  g_co);
    cudaGetSymbolAddress((void**)&gxf, g_gxf);
    cudaGetSymbolAddress((void**)&gxb, g_gxb);
    cudaGetSymbolAddress((void**)&hh,  g_h);
    cudaGetSymbolAddress((void**)&lg,  g_lg);

    ln1_kernel<<<BT, 256>>>(hid_a, hid_b, ln1_g, ln1_b, xn);
    conv_gemm_kernel<<<dim3(BT / 64, 12), 256>>>(xn, w1, w2, w3, w4, b1, b2, b3, b4, cv);
    ln2_kernel<<<BT, 256>>>(cv, ln2_g, ln2_b, co);
    gemm_bias_kernel<<<dim3(BT / 64, 16), 256>>>(co, wx_f, bf, gxf, BT, G4, C4T);
    gemm_bias_kernel<<<dim3(BT / 64, 16), 256>>>(co, wx_b, bb, gxb, BT, G4, C4T);
    lstm_kernel<<<64, 512>>>(gxf, gxb, wh_f, wh_b, amask, hh);
    gemm_bias_kernel<<<dim3(BT / 64, 1), 256>>>(hh, wd, bd, lg, BT, LBL, 2 * HN);
    crf_kernel<<<BN, 32>>>(inputs, targets, trans, lg, (float*)d_out);
}

// round 3
// speedup vs baseline: 1.2483x; 1.2483x over previous
#include <cuda_runtime.h>
#include <math.h>
#include <stdint.h>

// Problem dims
#define BN   64
#define TN   512
#define BT   32768       // B*T
#define DN   1536        // 2*D_BERT
#define C1   192         // conv channels each
#define C4T  768         // 4*C
#define HN   256
#define G4   1024        // 4*H
#define LBL  20

// ---------------- scratch (static device memory; no allocations) -------------
__device__ float g_xn [ (size_t)BT * DN  ];   // LN1 output
__device__ float g_cv [ (size_t)BT * C4T ];   // conv+relu output
__device__ float g_co [ (size_t)BT * C4T ];   // LN2 output
__device__ float g_gxf[ (size_t)BT * G4  ];   // x@Wx_f + bf
__device__ float g_gxb[ (size_t)BT * G4  ];   // x@Wx_b + bb
__device__ float g_h  [ (size_t)BT * 2*HN];   // [hf|hb] concat per (b,t)
__device__ float g_lg [ (size_t)BT * LBL ];   // logits

// ---------------- helpers -----------------------------------------------------
__device__ __forceinline__ uint32_t f2tf32(float f) {
    uint32_t u;
    asm("cvt.rna.tf32.f32 %0, %1;" : "=r"(u) : "f"(f));
    return u;
}

__device__ __forceinline__ void mma_tf32(float* c, uint32_t a0, uint32_t a1,
                                         uint32_t a2, uint32_t a3,
                                         uint32_t b0, uint32_t b1) {
    asm volatile(
        "mma.sync.aligned.m16n8k8.row.col.f32.tf32.tf32.f32 "
        "{%0,%1,%2,%3}, {%4,%5,%6,%7}, {%8,%9}, {%0,%1,%2,%3};\n"
        : "+f"(c[0]), "+f"(c[1]), "+f"(c[2]), "+f"(c[3])
        : "r"(a0), "r"(a1), "r"(a2), "r"(a3), "r"(b0), "r"(b1));
}

// Smem strides chosen for conflict-free fragment loads:
//  A stored [m][k] stride 36: bank = (4g+tg)%32 unique over (g,tg)
//  B stored [k][n] stride 68: bank = (4tg+g)%32 unique over (tg,g)
#define AST 36
#define BST 68

// ---------------- LayerNorm 1: concat(hid_a,hid_b) + LN over 1536 ------------
__global__ __launch_bounds__(256) void ln1_kernel(
    const float* __restrict__ ha, const float* __restrict__ hb,
    const float* __restrict__ g,  const float* __restrict__ be,
    float* __restrict__ out)
{
    int row = blockIdx.x;
    const float* A = ha + (size_t)row * 768;
    const float* B = hb + (size_t)row * 768;
    float s = 0.f, s2 = 0.f;
    for (int d = threadIdx.x; d < DN; d += 256) {
        float v = (d < 768) ? A[d] : B[d - 768];
        s += v; s2 += v * v;
    }
    __shared__ float rs[256], rq[256];
    rs[threadIdx.x] = s; rq[threadIdx.x] = s2;
    __syncthreads();
    for (int off = 128; off > 0; off >>= 1) {
        if (threadIdx.x < off) {
            rs[threadIdx.x] += rs[threadIdx.x + off];
            rq[threadIdx.x] += rq[threadIdx.x + off];
        }
        __syncthreads();
    }
    float mean = rs[0] * (1.f / DN);
    float var  = rq[0] * (1.f / DN) - mean * mean;
    float rstd = rsqrtf(var + 1e-5f);
    float* O = out + (size_t)row * DN;
    for (int d = threadIdx.x; d < DN; d += 256) {
        float v = (d < 768) ? A[d] : B[d - 768];
        O[d] = (v - mean) * rstd * g[d] + be[d];
    }
}

// ---------------- LayerNorm 2 over 768 ---------------------------------------
__global__ __launch_bounds__(256) void ln2_kernel(
    const float* __restrict__ in, const float* __restrict__ g,
    const float* __restrict__ be, float* __restrict__ out)
{
    int row = blockIdx.x;
    const float* X = in + (size_t)row * C4T;
    float s = 0.f, s2 = 0.f;
    for (int d = threadIdx.x; d < C4T; d += 256) {
        float v = X[d]; s += v; s2 += v * v;
    }
    __shared__ float rs[256], rq[256];
    rs[threadIdx.x] = s; rq[threadIdx.x] = s2;
    __syncthreads();
    for (int off = 128; off > 0; off >>= 1) {
        if (threadIdx.x < off) {
            rs[threadIdx.x] += rs[threadIdx.x + off];
            rq[threadIdx.x] += rq[threadIdx.x + off];
        }
        __syncthreads();
    }
    float mean = rs[0] * (1.f / C4T);
    float var  = rq[0] * (1.f / C4T) - mean * mean;
    float rstd = rsqrtf(var + 1e-5f);
    float* O = out + (size_t)row * C4T;
    for (int d = threadIdx.x; d < C4T; d += 256) {
        O[d] = (X[d] - mean) * rstd * g[d] + be[d];
    }
}

// ---------------- TF32 tensor-core GEMM: C = A[MxK]@W[KxN] + bias ------------
// Block tile 128x64, K-tile 32, 256 threads (8 warps, 4M x 2N), warp tile 32x32.
// M % 128 == 0, K % 32 == 0. N guarded.
__global__ __launch_bounds__(256) void gemm_tf32_kernel(
    const float* __restrict__ A, const float* __restrict__ W,
    const float* __restrict__ bias, float* __restrict__ C,
    int M, int N, int K, int relu)
{
    __shared__ uint32_t As[128 * AST];
    __shared__ uint32_t Bs[32 * BST];

    int tid = threadIdx.x;
    int m0 = blockIdx.x * 128, n0 = blockIdx.y * 64;
    int wid = tid >> 5, lane = tid & 31;
    int wm0 = (wid & 3) * 32, wn0 = (wid >> 2) * 32;
    int g = lane >> 2, tg = lane & 3;

    float acc[2][4][4];
#pragma unroll
    for (int mt = 0; mt < 2; mt++)
#pragma unroll
        for (int nt = 0; nt < 4; nt++)
#pragma unroll
            for (int i = 0; i < 4; i++) acc[mt][nt][i] = 0.f;

    // staging reg assignments
    // A: 4 float4 per thread, idx4 = tid + j*256 in [0,1024): row=idx4>>3, kc=(idx4&7)*4
    // B: 2 float4 per thread, idx4 = tid + j*256 in [0,512):  row=idx4>>4, nc=(idx4&15)*4
    float4 pa[4], pb[2];
    int nk = K / 32;

    auto loadA = [&](int kt) {
#pragma unroll
        for (int j = 0; j < 4; j++) {
            int idx4 = tid + j * 256;
            int row = idx4 >> 3, kc = (idx4 & 7) << 2;
            pa[j] = *reinterpret_cast<const float4*>(A + (size_t)(m0 + row) * K + kt * 32 + kc);
        }
    };
    auto loadB = [&](int kt) {
#pragma unroll
        for (int j = 0; j < 2; j++) {
            int idx4 = tid + j * 256;
            int row = idx4 >> 4, nc = (idx4 & 15) << 2;
            int ncol = n0 + nc;
            const float* Wr = W + (size_t)(kt * 32 + row) * N;
            float4 v;
            if (ncol + 3 < N) {
                v = *reinterpret_cast<const float4*>(Wr + ncol);
            } else {
                v.x = (ncol + 0 < N) ? Wr[ncol + 0] : 0.f;
                v.y = (ncol + 1 < N) ? Wr[ncol + 1] : 0.f;
                v.z = (ncol + 2 < N) ? Wr[ncol + 2] : 0.f;
                v.w = (ncol + 3 < N) ? Wr[ncol + 3] : 0.f;
            }
            pb[j] = v;
        }
    };
    auto stage = [&]() {
#pragma unroll
        for (int j = 0; j < 4; j++) {
            int idx4 = tid + j * 256;
            int row = idx4 >> 3, kc = (idx4 & 7) << 2;
            As[row * AST + kc + 0] = f2tf32(pa[j].x);
            As[row * AST + kc + 1] = f2tf32(pa[j].y);
            As[row * AST + kc + 2] = f2tf32(pa[j].z);
            As[row * AST + kc + 3] = f2tf32(pa[j].w);
        }
#pragma unroll
        for (int j = 0; j < 2; j++) {
            int idx4 = tid + j * 256;
            int row = idx4 >> 4, nc = (idx4 & 15) << 2;
            Bs[row * BST + nc + 0] = f2tf32(pb[j].x);
            Bs[row * BST + nc + 1] = f2tf32(pb[j].y);
            Bs[row * BST + nc + 2] = f2tf32(pb[j].z);
            Bs[row * BST + nc + 3] = f2tf32(pb[j].w);
        }
    };

    loadA(0); loadB(0);
    for (int kt = 0; kt < nk; kt++) {
        __syncthreads();
        stage();
        __syncthreads();
        if (kt + 1 < nk) { loadA(kt + 1); loadB(kt + 1); }
#pragma unroll
        for (int ks = 0; ks < 4; ks++) {
            int kk = ks * 8;
            uint32_t a[2][4], b[4][2];
#pragma unroll
            for (int mt = 0; mt < 2; mt++) {
                int r0 = wm0 + mt * 16 + g;
                a[mt][0] = As[(r0    ) * AST + kk + tg];
                a[mt][1] = As[(r0 + 8) * AST + kk + tg];
                a[mt][2] = As[(r0    ) * AST + kk + tg + 4];
                a[mt][3] = As[(r0 + 8) * AST + kk + tg + 4];
            }
#pragma unroll
            for (int nt = 0; nt < 4; nt++) {
                int col = wn0 + nt * 8 + g;
                b[nt][0] = Bs[(kk + tg    ) * BST + col];
                b[nt][1] = Bs[(kk + tg + 4) * BST + col];
            }
#pragma unroll
            for (int mt = 0; mt < 2; mt++)
#pragma unroll
                for (int nt = 0; nt < 4; nt++)
                    mma_tf32(acc[mt][nt], a[mt][0], a[mt][1], a[mt][2], a[mt][3],
                             b[nt][0], b[nt][1]);
        }
    }

    // epilogue
#pragma unroll
    for (int mt = 0; mt < 2; mt++) {
#pragma unroll
        for (int nt = 0; nt < 4; nt++) {
            int col = n0 + wn0 + nt * 8 + 2 * tg;
#pragma unroll
            for (int i = 0; i < 4; i++) {
                int row = m0 + wm0 + mt * 16 + g + (i >> 1) * 8;
                int c = col + (i & 1);
                if (c < N) {
                    float v = acc[mt][nt][i] + bias[c];
                    if (relu) v = fmaxf(v, 0.f);
                    C[(size_t)row * N + c] = v;
                }
            }
        }
    }
}

// ---------------- Conv (taps -1..+2) as TF32 GEMM, fused bias+ReLU -----------
__global__ __launch_bounds__(256) void conv_tf32_kernel(
    const float* __restrict__ xn,
    const float* __restrict__ w1, const float* __restrict__ w2,
    const float* __restrict__ w3, const float* __restrict__ w4,
    const float* __restrict__ b1, const float* __restrict__ b2,
    const float* __restrict__ b3, const float* __restrict__ b4,
    float* __restrict__ cv)
{
    __shared__ uint32_t As[128 * AST];
    __shared__ uint32_t Bs[32 * BST];

    int tid = threadIdx.x;
    int m0 = blockIdx.x * 128;
    int ct = blockIdx.y;            // 0..11
    int conv = ct / 3;
    int nloc0 = (ct % 3) * 64;
    int bidx = m0 >> 9;
    int t0   = m0 & 511;            // 128-row tiles never cross batch
    const float* wbase = (conv == 0) ? w1 : (conv == 1) ? w2 : (conv == 2) ? w3 : w4;
    const float* bias  = (conv == 0) ? b1 : (conv == 1) ? b2 : (conv == 2) ? b3 : b4;
    int ntaps = conv + 1;
    int dmin  = (conv < 2) ? 1 : 0;

    int wid = tid >> 5, lane = tid & 31;
    int wm0 = (wid & 3) * 32, wn0 = (wid >> 2) * 32;
    int g = lane >> 2, tg = lane & 3;

    float acc[2][4][4];
#pragma unroll
    for (int mt = 0; mt < 2; mt++)
#pragma unroll
        for (int nt = 0; nt < 4; nt++)
#pragma unroll
            for (int i = 0; i < 4; i++) acc[mt][nt][i] = 0.f;

    const int nk = DN / 32;          // 48
    int total = ntaps * nk;

    float4 pa[4], pb[2];
    auto loadA = [&](int it) {
        int ti = it / nk, kt = it % nk;
        int shift = dmin + ti - 1;
#pragma unroll
        for (int j = 0; j < 4; j++) {
            int idx4 = tid + j * 256;
            int row = idx4 >> 3, kc = (idx4 & 7) << 2;
            int tsrc = t0 + row + shift;
            if (tsrc >= 0 && tsrc < TN)
                pa[j] = *reinterpret_cast<const float4*>(
                    xn + (size_t)((bidx << 9) + tsrc) * DN + kt * 32 + kc);
            else
                pa[j] = make_float4(0.f, 0.f, 0.f, 0.f);
        }
    };
    auto loadB = [&](int it) {
        int ti = it / nk, kt = it % nk;
        const float* Wt = wbase + (size_t)ti * DN * C1 + nloc0;
#pragma unroll
        for (int j = 0; j < 2; j++) {
            int idx4 = tid + j * 256;
            int row = idx4 >> 4, nc = (idx4 & 15) << 2;
            pb[j] = *reinterpret_cast<const float4*>(Wt + (size_t)(kt * 32 + row) * C1 + nc);
        }
    };
    auto stage = [&]() {
#pragma unroll
        for (int j = 0; j < 4; j++) {
            int idx4 = tid + j * 256;
            int row = idx4 >> 3, kc = (idx4 & 7) << 2;
            As[row * AST + kc + 0] = f2tf32(pa[j].x);
            As[row * AST + kc + 1] = f2tf32(pa[j].y);
            As[row * AST + kc + 2] = f2tf32(pa[j].z);
            As[row * AST + kc + 3] = f2tf32(pa[j].w);
        }
#pragma unroll
        for (int j = 0; j < 2; j++) {
            int idx4 = tid + j * 256;
            int row = idx4 >> 4, nc = (idx4 & 15) << 2;
            Bs[row * BST + nc + 0] = f2tf32(pb[j].x);
            Bs[row * BST + nc + 1] = f2tf32(pb[j].y);
            Bs[row * BST + nc + 2] = f2tf32(pb[j].z);
            Bs[row * BST + nc + 3] = f2tf32(pb[j].w);
        }
    };

    loadA(0); loadB(0);
    for (int it = 0; it < total; it++) {
        __syncthreads();
        stage();
        __syncthreads();
        if (it + 1 < total) { loadA(it + 1); loadB(it + 1); }
#pragma unroll
        for (int ks = 0; ks < 4; ks++) {
            int kk = ks * 8;
            uint32_t a[2][4], b[4][2];
#pragma unroll
            for (int mt = 0; mt < 2; mt++) {
                int r0 = wm0 + mt * 16 + g;
                a[mt][0] = As[(r0    ) * AST + kk + tg];
                a[mt][1] = As[(r0 + 8) * AST + kk + tg];
                a[mt][2] = As[(r0    ) * AST + kk + tg + 4];
                a[mt][3] = As[(r0 + 8) * AST + kk + tg + 4];
            }
#pragma unroll
            for (int nt = 0; nt < 4; nt++) {
                int col = wn0 + nt * 8 + g;
                b[nt][0] = Bs[(kk + tg    ) * BST + col];
                b[nt][1] = Bs[(kk + tg + 4) * BST + col];
            }
#pragma unroll
            for (int mt = 0; mt < 2; mt++)
#pragma unroll
                for (int nt = 0; nt < 4; nt++)
                    mma_tf32(acc[mt][nt], a[mt][0], a[mt][1], a[mt][2], a[mt][3],
                             b[nt][0], b[nt][1]);
        }
    }

    // epilogue: bias + relu into cv at columns conv*192 + nloc0 + ...
#pragma unroll
    for (int mt = 0; mt < 2; mt++) {
#pragma unroll
        for (int nt = 0; nt < 4; nt++) {
            int cl = wn0 + nt * 8 + 2 * tg;              // 0..63 local
#pragma unroll
            for (int i = 0; i < 4; i++) {
                int row = m0 + wm0 + mt * 16 + g + (i >> 1) * 8;
                int c   = cl + (i & 1);
                float v = acc[mt][nt][i] + bias[nloc0 + c];
                cv[(size_t)row * C4T + conv * C1 + nloc0 + c] = fmaxf(v, 0.f);
            }
        }
    }
}

// ---------------- LSTM recurrence: block = (dir, batch-pair) -----------------
__global__ __launch_bounds__(512) void lstm_kernel(
    const float* __restrict__ gxf, const float* __restrict__ gxb,
    const float* __restrict__ wh_f, const float* __restrict__ wh_b,
    const int* __restrict__ amask, float* __restrict__ hout)
{
    int blk = blockIdx.x;
    int dir = blk >> 5;
    int bp  = blk & 31;
    int b0  = bp * 2;
    const float* Wh = dir ? wh_b : wh_f;   // [256][1024]
    const float* gx = dir ? gxb : gxf;     // [BT][1024]

    __shared__ float h_s[2][HN], c_s[2][HN], op_s[2][HN];
    __shared__ float z_s[2][G4];
    int tid = threadIdx.x;
    if (tid < HN) {
        h_s[0][tid] = 0.f; c_s[0][tid] = 0.f; op_s[0][tid] = 0.f;
        h_s[1][tid] = 0.f; c_s[1][tid] = 0.f; op_s[1][tid] = 0.f;
    }
    __syncthreads();

    for (int s = 0; s < TN; s++) {
        int t = dir ? (TN - 1 - s) : s;
        size_t r0 = ((size_t)(b0 * TN + t)) * G4;
        size_t r1 = ((size_t)((b0 + 1) * TN + t)) * G4;
        float a00 = gx[r0 + tid],       a01 = gx[r0 + tid + 512];
        float a10 = gx[r1 + tid],       a11 = gx[r1 + tid + 512];
#pragma unroll 4
        for (int k = 0; k < HN; k++) {
            float w0 = Wh[k * G4 + tid];
            float w1 = Wh[k * G4 + tid + 512];
            float h0 = h_s[0][k], h1 = h_s[1][k];
            a00 += h0 * w0; a01 += h0 * w1;
            a10 += h1 * w0; a11 += h1 * w1;
        }
        z_s[0][tid] = a00; z_s[0][tid + 512] = a01;
        z_s[1][tid] = a10; z_s[1][tid + 512] = a11;
        __syncthreads();
        {
            int q = tid >> 8, j = tid & 255;
            float zi = z_s[q][j],       zf = z_s[q][j + 256];
            float zg = z_s[q][j + 512], zo = z_s[q][j + 768];
            float ii = 1.f / (1.f + expf(-zi));
            float ff = 1.f / (1.f + expf(-zf));
            float gg = tanhf(zg);
            float oo = 1.f / (1.f + expf(-zo));
            float cn = ff * c_s[q][j] + ii * gg;
            float hn = oo * tanhf(cn);
            int bb_ = b0 + q;
            bool m = amask[bb_ * TN + t] != 0;
            float hq  = m ? hn : h_s[q][j];
            float cq  = m ? cn : c_s[q][j];
            float ov  = m ? hn : op_s[q][j];
            h_s[q][j] = hq; c_s[q][j] = cq; op_s[q][j] = ov;
            hout[((size_t)(bb_ * TN + t)) * (2 * HN) + dir * HN + j] = ov;
        }
        __syncthreads();
    }
}

// ---------------- CRF log-likelihood: one warp per batch element -------------
__global__ __launch_bounds__(32) void crf_kernel(
    const int* __restrict__ inputs, const int* __restrict__ targets,
    const float* __restrict__ trans, const float* __restrict__ logits,
    float* __restrict__ out)
{
    int b = blockIdx.x;
    int lane = threadIdx.x;
    __shared__ float tr[LBL * LBL];
    __shared__ float alpha[LBL];
    for (int i = lane; i < LBL * LBL; i += 32) tr[i] = trans[i];

    int cnt = 0;
    for (int t = lane; t < TN; t += 32) cnt += (inputs[b * TN + t] != 0);
#pragma unroll
    for (int o = 16; o; o >>= 1) cnt += __shfl_xor_sync(0xffffffffu, cnt, o);
    int seqlen = cnt;

    const float* lg = logits + (size_t)b * TN * LBL;
    const int*   tg = targets + b * TN;

    float us = 0.f, bs = 0.f;
    for (int t = lane; t < TN; t += 32) {
        if (t < seqlen) us += lg[t * LBL + tg[t]];
        if (t >= 1 && t < seqlen) bs += tr[tg[t - 1] * LBL + tg[t]];
    }
#pragma unroll
    for (int o = 16; o; o >>= 1) {
        us += __shfl_xor_sync(0xffffffffu, us, o);
        bs += __shfl_xor_sync(0xffffffffu, bs, o);
    }

    __syncwarp();
    if (lane < LBL) alpha[lane] = lg[lane];
    __syncwarp();

    for (int t = 1; t < TN; t++) {
        float newv = 0.f;
        if (lane < LBL) {
            float m = -1e30f;
#pragma unroll
            for (int i = 0; i < LBL; i++) m = fmaxf(m, alpha[i] + tr[i * LBL + lane]);
            float ss = 0.f;
#pragma unroll
            for (int i = 0; i < LBL; i++) ss += expf(alpha[i] + tr[i * LBL + lane] - m);
            newv = m + logf(ss) + lg[t * LBL + lane];
        }
        __syncwarp();
        if (lane < LBL && t < seqlen) alpha[lane] = newv;
        __syncwarp();
    }

    float a = (lane < LBL) ? alpha[lane] : -1e30f;
    float mx = a;
#pragma unroll
    for (int o = 16; o; o >>= 1) mx = fmaxf(mx, __shfl_xor_sync(0xffffffffu, mx, o));
    float e = (lane < LBL) ? expf(a - mx) : 0.f;
#pragma unroll
    for (int o = 16; o; o >>= 1) e += __shfl_xor_sync(0xffffffffu, e, o);
    float lognorm = mx + logf(e);
    if (lane == 0) out[b] = us + bs - lognorm;
}

// ---------------- launch ------------------------------------------------------
extern "C" void kernel_launch(void* const* d_in, const int* in_sizes, int n_in,
                              void* d_out, int out_size)
{
    const int*   inputs = (const int*)  d_in[0];
    const int*   amask  = (const int*)  d_in[1];
    const int*   targets= (const int*)  d_in[2];
    const float* hid_a  = (const float*)d_in[3];
    const float* hid_b  = (const float*)d_in[4];
    const float* ln1_g  = (const float*)d_in[5];
    const float* ln1_b  = (const float*)d_in[6];
    const float* w1 = (const float*)d_in[7];
    const float* b1 = (const float*)d_in[8];
    const float* w2 = (const float*)d_in[9];
    const float* b2 = (const float*)d_in[10];
    const float* w3 = (const float*)d_in[11];
    const float* b3 = (const float*)d_in[12];
    const float* w4 = (const float*)d_in[13];
    const float* b4 = (const float*)d_in[14];
    const float* ln2_g = (const float*)d_in[15];
    const float* ln2_b = (const float*)d_in[16];
    const float* wx_f  = (const float*)d_in[17];
    const float* wh_f  = (const float*)d_in[18];
    const float* bf    = (const float*)d_in[19];
    const float* wx_b  = (const float*)d_in[20];
    const float* wh_b  = (const float*)d_in[21];
    const float* bb    = (const float*)d_in[22];
    const float* wd    = (const float*)d_in[23];
    const float* bd    = (const float*)d_in[24];
    const float* trans = (const float*)d_in[25];

    float *xn, *cv, *co, *gxf, *gxb, *hh, *lg;
    cudaGetSymbolAddress((void**)&xn,  g_xn);
    cudaGetSymbolAddress((void**)&cv,  g_cv);
    cudaGetSymbolAddress((void**)&co,  g_co);
    cudaGetSymbolAddress((void**)&gxf, g_gxf);
    cudaGetSymbolAddress((void**)&gxb, g_gxb);
    cudaGetSymbolAddress((void**)&hh,  g_h);
    cudaGetSymbolAddress((void**)&lg,  g_lg);

    ln1_kernel<<<BT, 256>>>(hid_a, hid_b, ln1_g, ln1_b, xn);
    conv_tf32_kernel<<<dim3(BT / 128, 12), 256>>>(xn, w1, w2, w3, w4, b1, b2, b3, b4, cv);
    ln2_kernel<<<BT, 256>>>(cv, ln2_g, ln2_b, co);
    gemm_tf32_kernel<<<dim3(BT / 128, 16), 256>>>(co, wx_f, bf, gxf, BT, G4, C4T, 0);
    gemm_tf32_kernel<<<dim3(BT / 128, 16), 256>>>(co, wx_b, bb, gxb, BT, G4, C4T, 0);
    lstm_kernel<<<64, 512>>>(gxf, gxb, wh_f, wh_b, amask, hh);
    gemm_tf32_kernel<<<dim3(BT / 128, 1), 256>>>(hh, wd, bd, lg, BT, LBL, 2 * HN, 0);
    crf_kernel<<<BN, 32>>>(inputs, targets, trans, lg, (float*)d_out);
}

// round 4
// speedup vs baseline: 2.4288x; 1.9457x over previous
#include <cuda_runtime.h>
#include <math.h>
#include <stdint.h>

// Problem dims
#define BN   64
#define TN   512
#define BT   32768       // B*T
#define DN   1536        // 2*D_BERT
#define C1   192         // conv channels each
#define C4T  768         // 4*C
#define HN   256
#define G4   1024        // 4*H
#define LBL  20

// ---------------- scratch (static device memory; no allocations) -------------
__device__ float g_xn [ (size_t)BT * DN  ];   // LN1 output
__device__ float g_cv [ (size_t)BT * C4T ];   // conv+relu output
__device__ float g_co [ (size_t)BT * C4T ];   // LN2 output
__device__ float g_gxf[ (size_t)BT * G4  ];   // x@Wx_f + bf
__device__ float g_gxb[ (size_t)BT * G4  ];   // x@Wx_b + bb
__device__ float g_h  [ (size_t)BT * 2*HN];   // [hf|hb] concat per (b,t)
__device__ float g_lg [ (size_t)BT * LBL ];   // logits

// ---------------- helpers -----------------------------------------------------
__device__ __forceinline__ uint32_t f2tf32(float f) {
    uint32_t u;
    asm("cvt.rna.tf32.f32 %0, %1;" : "=r"(u) : "f"(f));
    return u;
}

__device__ __forceinline__ void mma_tf32(float* c, uint32_t a0, uint32_t a1,
                                         uint32_t a2, uint32_t a3,
                                         uint32_t b0, uint32_t b1) {
    asm volatile(
        "mma.sync.aligned.m16n8k8.row.col.f32.tf32.tf32.f32 "
        "{%0,%1,%2,%3}, {%4,%5,%6,%7}, {%8,%9}, {%0,%1,%2,%3};\n"
        : "+f"(c[0]), "+f"(c[1]), "+f"(c[2]), "+f"(c[3])
        : "r"(a0), "r"(a1), "r"(a2), "r"(a3), "r"(b0), "r"(b1));
}

#define AST 36
#define BST 68

// ---------------- LayerNorm 1: concat(hid_a,hid_b) + LN over 1536 ------------
__global__ __launch_bounds__(256) void ln1_kernel(
    const float* __restrict__ ha, const float* __restrict__ hb,
    const float* __restrict__ g,  const float* __restrict__ be,
    float* __restrict__ out)
{
    int row = blockIdx.x;
    const float* A = ha + (size_t)row * 768;
    const float* B = hb + (size_t)row * 768;
    float s = 0.f, s2 = 0.f;
    for (int d = threadIdx.x; d < DN; d += 256) {
        float v = (d < 768) ? A[d] : B[d - 768];
        s += v; s2 += v * v;
    }
    __shared__ float rs[256], rq[256];
    rs[threadIdx.x] = s; rq[threadIdx.x] = s2;
    __syncthreads();
    for (int off = 128; off > 0; off >>= 1) {
        if (threadIdx.x < off) {
            rs[threadIdx.x] += rs[threadIdx.x + off];
            rq[threadIdx.x] += rq[threadIdx.x + off];
        }
        __syncthreads();
    }
    float mean = rs[0] * (1.f / DN);
    float var  = rq[0] * (1.f / DN) - mean * mean;
    float rstd = rsqrtf(var + 1e-5f);
    float* O = out + (size_t)row * DN;
    for (int d = threadIdx.x; d < DN; d += 256) {
        float v = (d < 768) ? A[d] : B[d - 768];
        O[d] = (v - mean) * rstd * g[d] + be[d];
    }
}

// ---------------- LayerNorm 2 over 768 ---------------------------------------
__global__ __launch_bounds__(256) void ln2_kernel(
    const float* __restrict__ in, const float* __restrict__ g,
    const float* __restrict__ be, float* __restrict__ out)
{
    int row = blockIdx.x;
    const float* X = in + (size_t)row * C4T;
    float s = 0.f, s2 = 0.f;
    for (int d = threadIdx.x; d < C4T; d += 256) {
        float v = X[d]; s += v; s2 += v * v;
    }
    __shared__ float rs[256], rq[256];
    rs[threadIdx.x] = s; rq[threadIdx.x] = s2;
    __syncthreads();
    for (int off = 128; off > 0; off >>= 1) {
        if (threadIdx.x < off) {
            rs[threadIdx.x] += rs[threadIdx.x + off];
            rq[threadIdx.x] += rq[threadIdx.x + off];
        }
        __syncthreads();
    }
    float mean = rs[0] * (1.f / C4T);
    float var  = rq[0] * (1.f / C4T) - mean * mean;
    float rstd = rsqrtf(var + 1e-5f);
    float* O = out + (size_t)row * C4T;
    for (int d = threadIdx.x; d < C4T; d += 256) {
        O[d] = (X[d] - mean) * rstd * g[d] + be[d];
    }
}

// ---------------- TF32 tensor-core GEMM: C = A[MxK]@W[KxN] + bias ------------
__global__ __launch_bounds__(256) void gemm_tf32_kernel(
    const float* __restrict__ A, const float* __restrict__ W,
    const float* __restrict__ bias, float* __restrict__ C,
    int M, int N, int K, int relu)
{
    __shared__ uint32_t As[128 * AST];
    __shared__ uint32_t Bs[32 * BST];

    int tid = threadIdx.x;
    int m0 = blockIdx.x * 128, n0 = blockIdx.y * 64;
    int wid = tid >> 5, lane = tid & 31;
    int wm0 = (wid & 3) * 32, wn0 = (wid >> 2) * 32;
    int g = lane >> 2, tg = lane & 3;

    float acc[2][4][4];
#pragma unroll
    for (int mt = 0; mt < 2; mt++)
#pragma unroll
        for (int nt = 0; nt < 4; nt++)
#pragma unroll
            for (int i = 0; i < 4; i++) acc[mt][nt][i] = 0.f;

    float4 pa[4], pb[2];
    int nk = K / 32;

    auto loadA = [&](int kt) {
#pragma unroll
        for (int j = 0; j < 4; j++) {
            int idx4 = tid + j * 256;
            int row = idx4 >> 3, kc = (idx4 & 7) << 2;
            pa[j] = *reinterpret_cast<const float4*>(A + (size_t)(m0 + row) * K + kt * 32 + kc);
        }
    };
    auto loadB = [&](int kt) {
#pragma unroll
        for (int j = 0; j < 2; j++) {
            int idx4 = tid + j * 256;
            int row = idx4 >> 4, nc = (idx4 & 15) << 2;
            int ncol = n0 + nc;
            const float* Wr = W + (size_t)(kt * 32 + row) * N;
            float4 v;
            if (ncol + 3 < N) {
                v = *reinterpret_cast<const float4*>(Wr + ncol);
            } else {
                v.x = (ncol + 0 < N) ? Wr[ncol + 0] : 0.f;
                v.y = (ncol + 1 < N) ? Wr[ncol + 1] : 0.f;
                v.z = (ncol + 2 < N) ? Wr[ncol + 2] : 0.f;
                v.w = (ncol + 3 < N) ? Wr[ncol + 3] : 0.f;
            }
            pb[j] = v;
        }
    };
    auto stage = [&]() {
#pragma unroll
        for (int j = 0; j < 4; j++) {
            int idx4 = tid + j * 256;
            int row = idx4 >> 3, kc = (idx4 & 7) << 2;
            As[row * AST + kc + 0] = f2tf32(pa[j].x);
            As[row * AST + kc + 1] = f2tf32(pa[j].y);
            As[row * AST + kc + 2] = f2tf32(pa[j].z);
            As[row * AST + kc + 3] = f2tf32(pa[j].w);
        }
#pragma unroll
        for (int j = 0; j < 2; j++) {
            int idx4 = tid + j * 256;
            int row = idx4 >> 4, nc = (idx4 & 15) << 2;
            Bs[row * BST + nc + 0] = f2tf32(pb[j].x);
            Bs[row * BST + nc + 1] = f2tf32(pb[j].y);
            Bs[row * BST + nc + 2] = f2tf32(pb[j].z);
            Bs[row * BST + nc + 3] = f2tf32(pb[j].w);
        }
    };

    loadA(0); loadB(0);
    for (int kt = 0; kt < nk; kt++) {
        __syncthreads();
        stage();
        __syncthreads();
        if (kt + 1 < nk) { loadA(kt + 1); loadB(kt + 1); }
#pragma unroll
        for (int ks = 0; ks < 4; ks++) {
            int kk = ks * 8;
            uint32_t a[2][4], b[4][2];
#pragma unroll
            for (int mt = 0; mt < 2; mt++) {
                int r0 = wm0 + mt * 16 + g;
                a[mt][0] = As[(r0    ) * AST + kk + tg];
                a[mt][1] = As[(r0 + 8) * AST + kk + tg];
                a[mt][2] = As[(r0    ) * AST + kk + tg + 4];
                a[mt][3] = As[(r0 + 8) * AST + kk + tg + 4];
            }
#pragma unroll
            for (int nt = 0; nt < 4; nt++) {
                int col = wn0 + nt * 8 + g;
                b[nt][0] = Bs[(kk + tg    ) * BST + col];
                b[nt][1] = Bs[(kk + tg + 4) * BST + col];
            }
#pragma unroll
            for (int mt = 0; mt < 2; mt++)
#pragma unroll
                for (int nt = 0; nt < 4; nt++)
                    mma_tf32(acc[mt][nt], a[mt][0], a[mt][1], a[mt][2], a[mt][3],
                             b[nt][0], b[nt][1]);
        }
    }

#pragma unroll
    for (int mt = 0; mt < 2; mt++) {
#pragma unroll
        for (int nt = 0; nt < 4; nt++) {
            int col = n0 + wn0 + nt * 8 + 2 * tg;
#pragma unroll
            for (int i = 0; i < 4; i++) {
                int row = m0 + wm0 + mt * 16 + g + (i >> 1) * 8;
                int c = col + (i & 1);
                if (c < N) {
                    float v = acc[mt][nt][i] + bias[c];
                    if (relu) v = fmaxf(v, 0.f);
                    C[(size_t)row * N + c] = v;
                }
            }
        }
    }
}

// ---------------- Conv (taps -1..+2) as TF32 GEMM, fused bias+ReLU -----------
__global__ __launch_bounds__(256) void conv_tf32_kernel(
    const float* __restrict__ xn,
    const float* __restrict__ w1, const float* __restrict__ w2,
    const float* __restrict__ w3, const float* __restrict__ w4,
    const float* __restrict__ b1, const float* __restrict__ b2,
    const float* __restrict__ b3, const float* __restrict__ b4,
    float* __restrict__ cv)
{
    __shared__ uint32_t As[128 * AST];
    __shared__ uint32_t Bs[32 * BST];

    int tid = threadIdx.x;
    int m0 = blockIdx.x * 128;
    int ct = blockIdx.y;            // 0..11
    int conv = ct / 3;
    int nloc0 = (ct % 3) * 64;
    int bidx = m0 >> 9;
    int t0   = m0 & 511;
    const float* wbase = (conv == 0) ? w1 : (conv == 1) ? w2 : (conv == 2) ? w3 : w4;
    const float* bias  = (conv == 0) ? b1 : (conv == 1) ? b2 : (conv == 2) ? b3 : b4;
    int ntaps = conv + 1;
    int dmin  = (conv < 2) ? 1 : 0;

    int wid = tid >> 5, lane = tid & 31;
    int wm0 = (wid & 3) * 32, wn0 = (wid >> 2) * 32;
    int g = lane >> 2, tg = lane & 3;

    float acc[2][4][4];
#pragma unroll
    for (int mt = 0; mt < 2; mt++)
#pragma unroll
        for (int nt = 0; nt < 4; nt++)
#pragma unroll
            for (int i = 0; i < 4; i++) acc[mt][nt][i] = 0.f;

    const int nk = DN / 32;          // 48
    int total = ntaps * nk;

    float4 pa[4], pb[2];
    auto loadA = [&](int it) {
        int ti = it / nk, kt = it % nk;
        int shift = dmin + ti - 1;
#pragma unroll
        for (int j = 0; j < 4; j++) {
            int idx4 = tid + j * 256;
            int row = idx4 >> 3, kc = (idx4 & 7) << 2;
            int tsrc = t0 + row + shift;
            if (tsrc >= 0 && tsrc < TN)
                pa[j] = *reinterpret_cast<const float4*>(
                    xn + (size_t)((bidx << 9) + tsrc) * DN + kt * 32 + kc);
            else
                pa[j] = make_float4(0.f, 0.f, 0.f, 0.f);
        }
    };
    auto loadB = [&](int it) {
        int ti = it / nk, kt = it % nk;
        const float* Wt = wbase + (size_t)ti * DN * C1 + nloc0;
#pragma unroll
        for (int j = 0; j < 2; j++) {
            int idx4 = tid + j * 256;
            int row = idx4 >> 4, nc = (idx4 & 15) << 2;
            pb[j] = *reinterpret_cast<const float4*>(Wt + (size_t)(kt * 32 + row) * C1 + nc);
        }
    };
    auto stage = [&]() {
#pragma unroll
        for (int j = 0; j < 4; j++) {
            int idx4 = tid + j * 256;
            int row = idx4 >> 3, kc = (idx4 & 7) << 2;
            As[row * AST + kc + 0] = f2tf32(pa[j].x);
            As[row * AST + kc + 1] = f2tf32(pa[j].y);
            As[row * AST + kc + 2] = f2tf32(pa[j].z);
            As[row * AST + kc + 3] = f2tf32(pa[j].w);
        }
#pragma unroll
        for (int j = 0; j < 2; j++) {
            int idx4 = tid + j * 256;
            int row = idx4 >> 4, nc = (idx4 & 15) << 2;
            Bs[row * BST + nc + 0] = f2tf32(pb[j].x);
            Bs[row * BST + nc + 1] = f2tf32(pb[j].y);
            Bs[row * BST + nc + 2] = f2tf32(pb[j].z);
            Bs[row * BST + nc + 3] = f2tf32(pb[j].w);
        }
    };

    loadA(0); loadB(0);
    for (int it = 0; it < total; it++) {
        __syncthreads();
        stage();
        __syncthreads();
        if (it + 1 < total) { loadA(it + 1); loadB(it + 1); }
#pragma unroll
        for (int ks = 0; ks < 4; ks++) {
            int kk = ks * 8;
            uint32_t a[2][4], b[4][2];
#pragma unroll
            for (int mt = 0; mt < 2; mt++) {
                int r0 = wm0 + mt * 16 + g;
                a[mt][0] = As[(r0    ) * AST + kk + tg];
                a[mt][1] = As[(r0 + 8) * AST + kk + tg];
                a[mt][2] = As[(r0    ) * AST + kk + tg + 4];
                a[mt][3] = As[(r0 + 8) * AST + kk + tg + 4];
            }
#pragma unroll
            for (int nt = 0; nt < 4; nt++) {
                int col = wn0 + nt * 8 + g;
                b[nt][0] = Bs[(kk + tg    ) * BST + col];
                b[nt][1] = Bs[(kk + tg + 4) * BST + col];
            }
#pragma unroll
            for (int mt = 0; mt < 2; mt++)
#pragma unroll
                for (int nt = 0; nt < 4; nt++)
                    mma_tf32(acc[mt][nt], a[mt][0], a[mt][1], a[mt][2], a[mt][3],
                             b[nt][0], b[nt][1]);
        }
    }

#pragma unroll
    for (int mt = 0; mt < 2; mt++) {
#pragma unroll
        for (int nt = 0; nt < 4; nt++) {
            int cl = wn0 + nt * 8 + 2 * tg;
#pragma unroll
            for (int i = 0; i < 4; i++) {
                int row = m0 + wm0 + mt * 16 + g + (i >> 1) * 8;
                int c   = cl + (i & 1);
                float v = acc[mt][nt][i] + bias[nloc0 + c];
                cv[(size_t)row * C4T + conv * C1 + nloc0 + c] = fmaxf(v, 0.f);
            }
        }
    }
}

// ---------------- LSTM recurrence (rewritten) --------------------------------
// 64 blocks = (dir, batch-pair), 512 threads.
// GEMM phase: thread = (ks = tid>>8 in {0,1}, c4 = tid&255). Each thread
// computes 4 consecutive gate cols for BOTH batches over its k-half using
// float4 (LDG.128) Wh loads -> Wh read exactly once per block per step.
// Partials in smem, summed in the pointwise phase.
__global__ __launch_bounds__(512) void lstm_kernel(
    const float* __restrict__ gxf, const float* __restrict__ gxb,
    const float* __restrict__ wh_f, const float* __restrict__ wh_b,
    const int* __restrict__ amask, float* __restrict__ hout)
{
    int blk = blockIdx.x;
    int dir = blk >> 5;
    int bp  = blk & 31;
    int b0  = bp * 2;
    const float* __restrict__ Wh = dir ? wh_b : wh_f;   // [256][1024]
    const float* __restrict__ gx = dir ? gxb : gxf;     // [BT][1024]

    __shared__ float h_s[2][HN], c_s[2][HN], op_s[2][HN];
    __shared__ float zp[2][2][G4];          // [ks][batch][col] partials

    int tid = threadIdx.x;
    int ks  = tid >> 8;          // 0/1 : k half
    int c4  = tid & 255;         // column group (4 cols)
    if (tid < HN) {
        h_s[0][tid] = 0.f; c_s[0][tid] = 0.f; op_s[0][tid] = 0.f;
        h_s[1][tid] = 0.f; c_s[1][tid] = 0.f; op_s[1][tid] = 0.f;
    }
    __syncthreads();

    const float* wbase = Wh + (size_t)(ks * 128) * G4 + (c4 << 2);
    const float* hrow0 = &h_s[0][ks * 128];
    const float* hrow1 = &h_s[1][ks * 128];

    for (int s = 0; s < TN; s++) {
        int t = dir ? (TN - 1 - s) : s;

        // ---- GEMM phase: z_partial[b][4c] over k half ----
        float4 a0 = make_float4(0.f, 0.f, 0.f, 0.f);
        float4 a1 = make_float4(0.f, 0.f, 0.f, 0.f);
        const float* wp = wbase;
#pragma unroll 8
        for (int k = 0; k < 128; k++) {
            float4 w = *reinterpret_cast<const float4*>(wp);
            wp += G4;
            float h0 = hrow0[k];
            float h1 = hrow1[k];
            a0.x += h0 * w.x; a0.y += h0 * w.y; a0.z += h0 * w.z; a0.w += h0 * w.w;
            a1.x += h1 * w.x; a1.y += h1 * w.y; a1.z += h1 * w.z; a1.w += h1 * w.w;
        }
        *reinterpret_cast<float4*>(&zp[ks][0][c4 << 2]) = a0;
        *reinterpret_cast<float4*>(&zp[ks][1][c4 << 2]) = a1;
        __syncthreads();

        // ---- pointwise: thread = (q = tid>>8, j = tid&255) ----
        {
            int q = tid >> 8, j = tid & 255;
            int bb_ = b0 + q;
            size_t base = ((size_t)(bb_ * TN + t)) * G4;
            float zi = zp[0][q][j      ] + zp[1][q][j      ] + gx[base + j      ];
            float zf = zp[0][q][j + 256] + zp[1][q][j + 256] + gx[base + j + 256];
            float zg = zp[0][q][j + 512] + zp[1][q][j + 512] + gx[base + j + 512];
            float zo = zp[0][q][j + 768] + zp[1][q][j + 768] + gx[base + j + 768];
            float ii = 1.f / (1.f + expf(-zi));
            float ff = 1.f / (1.f + expf(-zf));
            float gg = tanhf(zg);
            float oo = 1.f / (1.f + expf(-zo));
            float cn = ff * c_s[q][j] + ii * gg;
            float hn = oo * tanhf(cn);
            bool m = amask[bb_ * TN + t] != 0;
            float hq = m ? hn : h_s[q][j];
            float cq = m ? cn : c_s[q][j];
            float ov = m ? hn : op_s[q][j];
            h_s[q][j] = hq; c_s[q][j] = cq; op_s[q][j] = ov;
            hout[((size_t)(bb_ * TN + t)) * (2 * HN) + dir * HN + j] = ov;
        }
        __syncthreads();
    }
}

// ---------------- CRF log-likelihood: one warp per batch element -------------
__global__ __launch_bounds__(32) void crf_kernel(
    const int* __restrict__ inputs, const int* __restrict__ targets,
    const float* __restrict__ trans, const float* __restrict__ logits,
    float* __restrict__ out)
{
    int b = blockIdx.x;
    int lane = threadIdx.x;
    __shared__ float tr[LBL * LBL];
    __shared__ float alpha[LBL];
    for (int i = lane; i < LBL * LBL; i += 32) tr[i] = trans[i];

    int cnt = 0;
    for (int t = lane; t < TN; t += 32) cnt += (inputs[b * TN + t] != 0);
#pragma unroll
    for (int o = 16; o; o >>= 1) cnt += __shfl_xor_sync(0xffffffffu, cnt, o);
    int seqlen = cnt;

    const float* lg = logits + (size_t)b * TN * LBL;
    const int*   tg = targets + b * TN;

    float us = 0.f, bs = 0.f;
    for (int t = lane; t < TN; t += 32) {
        if (t < seqlen) us += lg[t * LBL + tg[t]];
        if (t >= 1 && t < seqlen) bs += tr[tg[t - 1] * LBL + tg[t]];
    }
#pragma unroll
    for (int o = 16; o; o >>= 1) {
        us += __shfl_xor_sync(0xffffffffu, us, o);
        bs += __shfl_xor_sync(0xffffffffu, bs, o);
    }

    __syncwarp();
    if (lane < LBL) alpha[lane] = lg[lane];
    __syncwarp();

    for (int t = 1; t < TN; t++) {
        float newv = 0.f;
        if (lane < LBL) {
            float m = -1e30f;
#pragma unroll
            for (int i = 0; i < LBL; i++) m = fmaxf(m, alpha[i] + tr[i * LBL + lane]);
            float ss = 0.f;
#pragma unroll
            for (int i = 0; i < LBL; i++) ss += expf(alpha[i] + tr[i * LBL + lane] - m);
            newv = m + logf(ss) + lg[t * LBL + lane];
        }
        __syncwarp();
        if (lane < LBL && t < seqlen) alpha[lane] = newv;
        __syncwarp();
    }

    float a = (lane < LBL) ? alpha[lane] : -1e30f;
    float mx = a;
#pragma unroll
    for (int o = 16; o; o >>= 1) mx = fmaxf(mx, __shfl_xor_sync(0xffffffffu, mx, o));
    float e = (lane < LBL) ? expf(a - mx) : 0.f;
#pragma unroll
    for (int o = 16; o; o >>= 1) e += __shfl_xor_sync(0xffffffffu, e, o);
    float lognorm = mx + logf(e);
    if (lane == 0) out[b] = us + bs - lognorm;
}

// ---------------- launch ------------------------------------------------------
extern "C" void kernel_launch(void* const* d_in, const int* in_sizes, int n_in,
                              void* d_out, int out_size)
{
    const int*   inputs = (const int*)  d_in[0];
    const int*   amask  = (const int*)  d_in[1];
    const int*   targets= (const int*)  d_in[2];
    const float* hid_a  = (const float*)d_in[3];
    const float* hid_b  = (const float*)d_in[4];
    const float* ln1_g  = (const float*)d_in[5];
    const float* ln1_b  = (const float*)d_in[6];
    const float* w1 = (const float*)d_in[7];
    const float* b1 = (const float*)d_in[8];
    const float* w2 = (const float*)d_in[9];
    const float* b2 = (const float*)d_in[10];
    const float* w3 = (const float*)d_in[11];
    const float* b3 = (const float*)d_in[12];
    const float* w4 = (const float*)d_in[13];
    const float* b4 = (const float*)d_in[14];
    const float* ln2_g = (const float*)d_in[15];
    const float* ln2_b = (const float*)d_in[16];
    const float* wx_f  = (const float*)d_in[17];
    const float* wh_f  = (const float*)d_in[18];
    const float* bf    = (const float*)d_in[19];
    const float* wx_b  = (const float*)d_in[20];
    const float* wh_b  = (const float*)d_in[21];
    const float* bb    = (const float*)d_in[22];
    const float* wd    = (const float*)d_in[23];
    const float* bd    = (const float*)d_in[24];
    const float* trans = (const float*)d_in[25];

    float *xn, *cv, *co, *gxf, *gxb, *hh, *lg;
    cudaGetSymbolAddress((void**)&xn,  g_xn);
    cudaGetSymbolAddress((void**)&cv,  g_cv);
    cudaGetSymbolAddress((void**)&co,  g_co);
    cudaGetSymbolAddress((void**)&gxf, g_gxf);
    cudaGetSymbolAddress((void**)&gxb, g_gxb);
    cudaGetSymbolAddress((void**)&hh,  g_h);
    cudaGetSymbolAddress((void**)&lg,  g_lg);

    ln1_kernel<<<BT, 256>>>(hid_a, hid_b, ln1_g, ln1_b, xn);
    conv_tf32_kernel<<<dim3(BT / 128, 12), 256>>>(xn, w1, w2, w3, w4, b1, b2, b3, b4, cv);
    ln2_kernel<<<BT, 256>>>(cv, ln2_g, ln2_b, co);
    gemm_tf32_kernel<<<dim3(BT / 128, 16), 256>>>(co, wx_f, bf, gxf, BT, G4, C4T, 0);
    gemm_tf32_kernel<<<dim3(BT / 128, 16), 256>>>(co, wx_b, bb, gxb, BT, G4, C4T, 0);
    lstm_kernel<<<64, 512>>>(gxf, gxb, wh_f, wh_b, amask, hh);
    gemm_tf32_kernel<<<dim3(BT / 128, 1), 256>>>(hh, wd, bd, lg, BT, LBL, 2 * HN, 0);
    crf_kernel<<<BN, 32>>>(inputs, targets, trans, lg, (float*)d_out);
}